// round 13
// baseline (speedup 1.0000x reference)
#include <cuda_runtime.h>
#include <cuda_bf16.h>
#include <math.h>
#include <stdint.h>

// Shapes (fixed by the problem)
#define NQ   10
#define NL   4
#define NG   (NL * NQ)   // 40 single-qubit gates
#define NDIM 1024        // 2^NQ amplitudes
#define FFN  4096
#define EDIM 1024
#define NTOK 16384       // B*T
#define GRID_A 137       // 0..7 h-rows, 8..135 matvec (128), 136 circuit

#define W2_BYTES_PER_BLOCK 131072u   // 8 rows x 16KB
#define W2_CHUNK           32768u

#define FILL_ROWS_STAGED   8         // 32KB smem
#define FILL_ROWS_PER_BLK  16        // 2 bulk stores of 32KB
#define FILL_GRID          (NTOK / FILL_ROWS_PER_BLK)   // 1024

// Persistent scratch / flags (monotonic across graph replays: no reset needed)
__device__ int g_entry = 0;
__device__ int g_zflag = 0;
__device__ int g_hcnt  = 0;
__device__ float g_z[16];
__device__ __align__(16) float g_h[FFN];
__device__ __align__(16) float g_y[EDIM];

__device__ __forceinline__ float2 cmul(float2 a, float2 b) {
    return make_float2(fmaf(a.x, b.x, -a.y * b.y), fmaf(a.x, b.y, a.y * b.x));
}
__device__ __forceinline__ float2 cfma2(float2 u, float2 a, float2 v, float2 b) {
    float re = fmaf(u.x, a.x, -u.y * a.y);
    re = fmaf(v.x, b.x, re);
    re = fmaf(-v.y, b.y, re);
    float im = fmaf(u.x, a.y, u.y * a.x);
    im = fmaf(v.x, b.y, im);
    im = fmaf(v.y, b.x, im);
    return make_float2(re, im);
}
__device__ __forceinline__ void l2_prefetch(const void* p) {
    asm volatile("prefetch.global.L2 [%0];" :: "l"(p));
}
__device__ __forceinline__ void mbar_wait_acq(uint32_t mbar, uint32_t parity) {
    uint32_t done = 0;
    while (!done) {
        asm volatile(
            "{\n\t.reg .pred p;\n\t"
            "mbarrier.try_wait.parity.acquire.cta.shared::cta.b64 p, [%1], %2, 0x989680;\n\t"
            "selp.b32 %0, 1, 0, p;\n\t}"
            : "=r"(done) : "r"(mbar), "r"(parity) : "memory");
    }
}

// padded smem index for stride-16 gathers
#define SIDX(i) ((i) + ((i) >> 4))
#define STSZ    (NDIM + NDIM / 16 + 8)

// ---------------------------------------------------------------------------
// Kernel A (everything except the fill):
//   block 136 : circuit -> g_z (layer 1 analytic; final ring folded into Z)
//   blocks 0..7: W1 rows in regs during circuit -> h -> g_h, bump hcnt
//   blocks 8..135: 8 W2 rows pulled into SMEM via cp.async.bulk (TMA path —
//                bypasses the per-SM LDG MLP limit) during circuit; then
//                y slice -> g_y
// ---------------------------------------------------------------------------
__global__ void __launch_bounds__(512, 1)
circuit_h_y_kernel(const float* __restrict__ params,
                   const float* __restrict__ W1,
                   const float* __restrict__ b1,
                   const float* __restrict__ W2,
                   const float* __restrict__ b2) {
    extern __shared__ __align__(128) unsigned char dynsm[];   // 128KB (y blocks)
    __shared__ float2 U[NG][2];
    __shared__ float2 st[2][STSZ];
    __shared__ float  wsum[16][NQ];
    __shared__ float  red[16];
    __shared__ __align__(8) uint64_t mbar;
    __shared__ int    s_epoch;

    const int t    = threadIdx.x;          // 0..511
    const int b    = blockIdx.x;
    const int lane = t & 31;
    const int warp = t >> 5;

    if (t == 0) s_epoch = atomicAdd(&g_entry, 1) / GRID_A;
    __syncthreads();
    const int target = s_epoch + 1;

    if (b < 8) {
        // ============ h rows: W1 row in regs while circuit runs ============
        const int j = b * 512 + t;               // row 0..4095
        const float* __restrict__ w = W1 + (size_t)j * NQ;
        float f[NQ];
        #pragma unroll
        for (int q = 0; q < NQ; q++) f[q] = w[q];
        const float bias = b1[j];

        if (t == 0) {
            while (((volatile int*)&g_zflag)[0] < target) __nanosleep(32);
        }
        __syncthreads();
        __threadfence();

        float acc = bias;
        #pragma unroll
        for (int q = 0; q < NQ; q++) acc = fmaf(f[q], g_z[q], acc);
        g_h[j] = fmaxf(acc, 0.0f);
        __threadfence();
        __syncthreads();
        if (t == 0) atomicAdd(&g_hcnt, 1);
        return;
    }

    if (b < 136) {
        // ====== y blocks: bulk-copy 8 W2 rows (128KB) into smem via TMA =====
        const int pb = b - 8;                     // 0..127
        float4* w2s = (float4*)dynsm;             // 8 rows x 1024 float4
        const uint32_t sdst = (uint32_t)__cvta_generic_to_shared(w2s);
        const uint32_t mb   = (uint32_t)__cvta_generic_to_shared(&mbar);
        const char* gsrc = (const char*)(W2 + (size_t)pb * 8 * FFN);

        if (t == 0) {
            asm volatile("mbarrier.init.shared.b64 [%0], %1;"
                         :: "r"(mb), "r"(1u) : "memory");
            asm volatile("mbarrier.arrive.expect_tx.shared.b64 _, [%0], %1;"
                         :: "r"(mb), "r"(W2_BYTES_PER_BLOCK) : "memory");
            #pragma unroll
            for (uint32_t c = 0; c < 4; c++) {
                asm volatile(
                    "cp.async.bulk.shared::cluster.global.mbarrier::complete_tx::bytes "
                    "[%0], [%1], %2, [%3];"
                    :: "r"(sdst + c * W2_CHUNK), "l"(gsrc + (size_t)c * W2_CHUNK),
                       "r"(W2_CHUNK), "r"(mb) : "memory");
            }
            l2_prefetch(b2 + pb * 8);
            // wait for all 8 h blocks while the bulk copies stream in
            const int ht = 8 * target;
            while (((volatile int*)&g_hcnt)[0] < ht) __nanosleep(32);
        }
        __syncthreads();
        __threadfence();
        mbar_wait_acq(mb, 0);   // W2 tile resident in smem

        const int g = t >> 6;                     // 0..7 output within block
        const int j = t & 63;
        const float4* __restrict__ h4 = (const float4*)g_h;
        float acc = 0.0f;
        #pragma unroll
        for (int k = 0; k < 16; k++) {
            const float4 w = w2s[g * 1024 + j + 64 * k];
            const float4 h = h4[j + 64 * k];
            acc += w.x * h.x + w.y * h.y + w.z * h.z + w.w * h.w;
        }
        #pragma unroll
        for (int o = 16; o > 0; o >>= 1) acc += __shfl_down_sync(0xffffffffu, acc, o);
        if (lane == 0) red[warp] = acc;
        __syncthreads();
        if (t < 8) g_y[pb * 8 + t] = red[2 * t] + red[2 * t + 1] + b2[pb * 8 + t];
        return;
    }

    // ===================== circuit (block 136) =====================
    if (t < NG) {
        const float t0 = params[t * 3 + 0];
        const float t1 = params[t * 3 + 1];
        const float t2 = params[t * 3 + 2];
        float cx, sx, cy, sy, cz, sz;
        sincosf(0.5f * t0, &sx, &cx);
        sincosf(0.5f * t1, &sy, &cy);
        sincosf(0.5f * t2, &sz, &cz);
        const float2 m00 = make_float2( cy * cx,  sy * sx);
        const float2 m01 = make_float2(-sy * cx, -cy * sx);
        const float2 ezm = make_float2(cz, -sz);
        U[t][0] = cmul(ezm, m00);   // u00
        U[t][1] = cmul(ezm, m01);   // u01 (u10=-conj(u01), u11=conj(u00))
    }

    // layout-B base index: bits[8:5]=lane[4:1], bit4=lane[0], bits[3:0]=warp
    const int iB = ((lane >> 1) << 5) | ((lane & 1) << 4) | warp;

    // forward ring permutation C (descending e): s_new[i] = s_old[C(i)]
    int Ct0 = t, Ct1 = t + 512;
    #pragma unroll
    for (int e = NQ - 1; e >= 0; e--) {
        const int c  = (e < NQ - 1) ? e : NQ - 1;
        const int tq = (e < NQ - 1) ? e + 1 : 0;
        const int cm = 1 << (NQ - 1 - c);
        const int tm = 1 << (NQ - 1 - tq);
        Ct0 ^= (Ct0 & cm) ? tm : 0;
        Ct1 ^= (Ct1 & cm) ? tm : 0;
    }
    // inverse ring C^-1 (ascending e) applied to layout-B indices we hold at
    // the end of layer 4 (the final gather is skipped; ring folded into Z)
    int Jf0 = iB, Jf1 = iB + 512;
    #pragma unroll
    for (int e = 0; e < NQ; e++) {
        const int c  = (e < NQ - 1) ? e : NQ - 1;
        const int tq = (e < NQ - 1) ? e + 1 : 0;
        const int cm = 1 << (NQ - 1 - c);
        const int tm = 1 << (NQ - 1 - tq);
        Jf0 ^= (Jf0 & cm) ? tm : 0;
        Jf1 ^= (Jf1 & cm) ? tm : 0;
    }

    float sgn[5];
    #pragma unroll
    for (int k = 0; k < 5; k++) sgn[k] = (lane & (16 >> k)) ? -1.0f : 1.0f;

    __syncthreads();   // U ready

    // ---- layer 1 analytic: a(i) = psi(C(i)), psi = product state ----------
    float2 a0, a1;
    {
        float2 p0, p1;
        #pragma unroll
        for (int q = 0; q < NQ; q++) {
            const float2 u00 = U[q][0];
            const float2 u01 = U[q][1];
            const float2 u10 = make_float2(-u01.x, u01.y);
            const float2 v0 = ((Ct0 >> (9 - q)) & 1) ? u10 : u00;
            const float2 v1 = ((Ct1 >> (9 - q)) & 1) ? u10 : u00;
            if (q == 0) { p0 = v0; p1 = v1; }
            else        { p0 = cmul(p0, v0); p1 = cmul(p1, v1); }
        }
        a0 = p0; a1 = p1;
    }

    // ---- layers 2..4 ------------------------------------------------------
    int cur = 0;
    #pragma unroll 1
    for (int l = 1; l < NL; l++) {
        // qubit 0: register bit (thread-local)
        {
            const int g = l * NQ;
            const float2 u00 = U[g][0], u01 = U[g][1];
            const float2 u10 = make_float2(-u01.x, u01.y);
            const float2 u11 = make_float2( u00.x, -u00.y);
            const float2 n0 = cfma2(u00, a0, u01, a1);
            const float2 n1 = cfma2(u10, a0, u11, a1);
            a0 = n0; a1 = n1;
        }
        // qubits 5..9 on lane bits (layout A)
        #pragma unroll
        for (int k = 0; k < 5; k++) {
            const int g = l * NQ + 5 + k;
            float2 u0 = U[g][0];
            float2 u1 = U[g][1];
            const float s = sgn[k];
            u0.y *= s; u1.x *= s;
            const int m = 16 >> k;
            float2 b0v, b1v;
            b0v.x = __shfl_xor_sync(0xffffffffu, a0.x, m);
            b0v.y = __shfl_xor_sync(0xffffffffu, a0.y, m);
            b1v.x = __shfl_xor_sync(0xffffffffu, a1.x, m);
            b1v.y = __shfl_xor_sync(0xffffffffu, a1.y, m);
            a0 = cfma2(u0, a0, u1, b0v);
            a1 = cfma2(u0, a1, u1, b1v);
        }
        // transpose A -> B
        st[cur][SIDX(t)]       = a0;
        st[cur][SIDX(t + 512)] = a1;
        __syncthreads();
        a0 = st[cur][SIDX(iB)];
        a1 = st[cur][SIDX(iB + 512)];
        cur ^= 1;
        // qubits 1..4 on lane bits 4..1 (layout B)
        #pragma unroll
        for (int k = 0; k < 4; k++) {
            const int g = l * NQ + 1 + k;
            float2 u0 = U[g][0];
            float2 u1 = U[g][1];
            const float s = sgn[k];
            u0.y *= s; u1.x *= s;
            const int m = 16 >> k;
            float2 b0v, b1v;
            b0v.x = __shfl_xor_sync(0xffffffffu, a0.x, m);
            b0v.y = __shfl_xor_sync(0xffffffffu, a0.y, m);
            b1v.x = __shfl_xor_sync(0xffffffffu, a1.x, m);
            b1v.y = __shfl_xor_sync(0xffffffffu, a1.y, m);
            a0 = cfma2(u0, a0, u1, b0v);
            a1 = cfma2(u0, a1, u1, b1v);
        }
        if (l < NL - 1) {
            st[cur][SIDX(iB)]       = a0;
            st[cur][SIDX(iB + 512)] = a1;
            __syncthreads();
            a0 = st[cur][SIDX(Ct0)];
            a1 = st[cur][SIDX(Ct1)];
            cur ^= 1;
        }
    }

    // <Z_q> with the final ring folded in
    const float p0 = fmaf(a0.x, a0.x, a0.y * a0.y);
    const float p1 = fmaf(a1.x, a1.x, a1.y * a1.y);
    #pragma unroll
    for (int q = 0; q < NQ; q++) {
        const int mask = 1 << (NQ - 1 - q);
        float v = ((Jf0 & mask) ? p0 : 0.0f) + ((Jf1 & mask) ? p1 : 0.0f);
        #pragma unroll
        for (int o = 16; o > 0; o >>= 1) v += __shfl_xor_sync(0xffffffffu, v, o);
        if (lane == 0) wsum[warp][q] = v;
    }
    __syncthreads();
    if (t < NQ) {
        float s = 0.0f;
        #pragma unroll
        for (int w = 0; w < 16; w++) s += wsum[w][t];
        g_z[t] = 1.0f - 2.0f * s;
    }
    __syncthreads();
    if (t == 0) {
        __threadfence();
        atomicMax(&g_zflag, target);   // release; monotonic
    }
}

// ---------------------------------------------------------------------------
// Kernel C: fill via TMA bulk stores. Stage 8 identical rows (32KB) in smem,
// then 2 x 32KB cp.async.bulk stores -> 16 rows per block. Bypasses the
// per-SM STG.128 issue cost that capped the STG fill at ~5.6 TB/s.
// ---------------------------------------------------------------------------
__global__ void __launch_bounds__(256)
fill_kernel(float4* __restrict__ out) {
    extern __shared__ __align__(128) unsigned char dynsm2[];
    float4* buf = (float4*)dynsm2;               // 2048 float4 = 32KB
    const int t = threadIdx.x;
    const float4 v = ((const float4*)g_y)[t];
    #pragma unroll
    for (int r = 0; r < FILL_ROWS_STAGED; r++) buf[r * 256 + t] = v;
    __syncthreads();
    if (t == 0) {
        asm volatile("fence.proxy.async.shared::cta;" ::: "memory");
        const uint32_t ssrc = (uint32_t)__cvta_generic_to_shared(buf);
        char* gdst = (char*)(out + (size_t)blockIdx.x * (FILL_ROWS_PER_BLK * 256));
        #pragma unroll
        for (int i = 0; i < FILL_ROWS_PER_BLK / FILL_ROWS_STAGED; i++) {
            asm volatile(
                "cp.async.bulk.global.shared::cta.bulk_group [%0], [%1], %2;"
                :: "l"(gdst + (size_t)i * 32768), "r"(ssrc), "r"(32768u) : "memory");
        }
        asm volatile("cp.async.bulk.commit_group;" ::: "memory");
        asm volatile("cp.async.bulk.wait_group 0;" ::: "memory");
    }
}

// ---------------------------------------------------------------------------
// inputs: 0=x, 1=W_in, 2=b_in, 3=params, 4=W1, 5=b1, 6=W2, 7=b2
// x / W_in / b_in are dead in the reference.
// ---------------------------------------------------------------------------
extern "C" void kernel_launch(void* const* d_in, const int* in_sizes, int n_in,
                              void* d_out, int out_size) {
    const float* params = (const float*)d_in[3];
    const float* W1     = (const float*)d_in[4];
    const float* b1     = (const float*)d_in[5];
    const float* W2     = (const float*)d_in[6];
    const float* b2     = (const float*)d_in[7];
    float* out = (float*)d_out;

    cudaFuncSetAttribute(circuit_h_y_kernel,
                         cudaFuncAttributeMaxDynamicSharedMemorySize, 131072);
    cudaFuncSetAttribute(fill_kernel,
                         cudaFuncAttributeMaxDynamicSharedMemorySize, 32768);

    circuit_h_y_kernel<<<GRID_A, 512, 131072>>>(params, W1, b1, W2, b2);
    fill_kernel<<<FILL_GRID, 256, 32768>>>((float4*)out);
}

// round 14
// speedup vs baseline: 1.0115x; 1.0115x over previous
#include <cuda_runtime.h>
#include <cuda_bf16.h>
#include <math.h>

// Shapes (fixed by the problem)
#define NQ   10
#define NL   4
#define NG   (NL * NQ)   // 40 single-qubit gates
#define NDIM 1024        // 2^NQ amplitudes
#define FFN  4096
#define EDIM 1024
#define NTOK 16384       // B*T
#define GRID_A 133       // 0..3 h-rows, 4..131 matvec (128), 132 circuit

// Persistent scratch / flags (monotonic across graph replays: no reset needed)
__device__ int g_entry = 0;
__device__ int g_zflag = 0;
__device__ int g_hcnt  = 0;
__device__ float g_z[16];
__device__ __align__(16) float g_h[FFN];
__device__ __align__(16) float g_y[EDIM];

__device__ __forceinline__ float2 cmul(float2 a, float2 b) {
    return make_float2(fmaf(a.x, b.x, -a.y * b.y), fmaf(a.x, b.y, a.y * b.x));
}
__device__ __forceinline__ float2 cfma2(float2 u, float2 a, float2 v, float2 b) {
    float re = fmaf(u.x, a.x, -u.y * a.y);
    re = fmaf(v.x, b.x, re);
    re = fmaf(-v.y, b.y, re);
    float im = fmaf(u.x, a.y, u.y * a.x);
    im = fmaf(v.x, b.y, im);
    im = fmaf(v.y, b.x, im);
    return make_float2(re, im);
}
__device__ __forceinline__ void l2_prefetch(const void* p) {
    asm volatile("prefetch.global.L2 [%0];" :: "l"(p));
}

// padded smem index for stride-32 transpose gathers
#define SIDX(i) ((i) + ((i) >> 5))
#define STSZ    (NDIM + NDIM / 32 + 8)

// ---------------------------------------------------------------------------
// Kernel A (everything except the fill). 1024 threads/block.
//   block 132 : circuit, 1 amplitude per thread (32 warps = 8/SMSP for
//               shfl-latency hiding). Layer 1 analytic; final ring folded
//               into the Z masks.
//   blocks 0..3: W1 rows in regs during circuit -> h -> g_h, bump hcnt
//   blocks 4..131: 8 W2 rows in regs during circuit -> y slice -> g_y
// ---------------------------------------------------------------------------
__global__ void __launch_bounds__(1024, 1)
circuit_h_y_kernel(const float* __restrict__ params,
                   const float* __restrict__ W1,
                   const float* __restrict__ b1,
                   const float* __restrict__ W2,
                   const float* __restrict__ b2) {
    __shared__ float2 U[NG][2];
    __shared__ float2 st[2][STSZ];
    __shared__ float  wsum[32][NQ];
    __shared__ float  red[32];
    __shared__ int    s_epoch;

    const int t    = threadIdx.x;          // 0..1023
    const int b    = blockIdx.x;
    const int lane = t & 31;
    const int warp = t >> 5;

    if (t == 0) s_epoch = atomicAdd(&g_entry, 1) / GRID_A;
    __syncthreads();
    const int target = s_epoch + 1;

    if (b < 4) {
        // ============ h rows: W1 row in regs while circuit runs ============
        const int j = b * 1024 + t;              // row 0..4095
        const float* __restrict__ w = W1 + (size_t)j * NQ;
        float f[NQ];
        #pragma unroll
        for (int q = 0; q < NQ; q++) f[q] = w[q];
        const float bias = b1[j];

        if (t == 0) {
            while (((volatile int*)&g_zflag)[0] < target) __nanosleep(32);
        }
        __syncthreads();
        __threadfence();

        float acc = bias;
        #pragma unroll
        for (int q = 0; q < NQ; q++) acc = fmaf(f[q], g_z[q], acc);
        g_h[j] = fmaxf(acc, 0.0f);
        __threadfence();
        __syncthreads();
        if (t == 0) atomicAdd(&g_hcnt, 1);
        return;
    }

    if (b < 132) {
        // ========= matvec blocks: y[8pb .. 8pb+8), W2 rows preloaded =========
        const int pb = b - 4;                     // 0..127
        const int g  = t >> 7;                    // 0..7 output within block
        const int j  = t & 127;
        const int e  = pb * 8 + g;
        const float4* __restrict__ w4 = (const float4*)(W2 + (size_t)e * FFN);

        #pragma unroll
        for (int k = 0; k < 8; k++) l2_prefetch(&w4[j + 128 * k]);
        if (t == 0) l2_prefetch(b2 + pb * 8);
        float4 w[8];
        #pragma unroll
        for (int k = 0; k < 8; k++) w[k] = w4[j + 128 * k];

        // wait for all 4 h blocks
        if (t == 0) {
            const int ht = 4 * target;
            while (((volatile int*)&g_hcnt)[0] < ht) __nanosleep(32);
        }
        __syncthreads();
        __threadfence();

        const float4* __restrict__ h4 = (const float4*)g_h;
        float acc = 0.0f;
        #pragma unroll
        for (int k = 0; k < 8; k++) {
            const float4 h = h4[j + 128 * k];
            acc += w[k].x * h.x + w[k].y * h.y + w[k].z * h.z + w[k].w * h.w;
        }
        #pragma unroll
        for (int o = 16; o > 0; o >>= 1) acc += __shfl_down_sync(0xffffffffu, acc, o);
        if (lane == 0) red[warp] = acc;
        __syncthreads();
        if (t < 8) {
            g_y[pb * 8 + t] = red[4 * t] + red[4 * t + 1] + red[4 * t + 2]
                            + red[4 * t + 3] + b2[pb * 8 + t];
        }
        return;
    }

    // ===================== circuit (block 132, 1 amp/thread) ===============
    if (t < NG) {
        const float t0 = params[t * 3 + 0];
        const float t1 = params[t * 3 + 1];
        const float t2 = params[t * 3 + 2];
        float cx, sx, cy, sy, cz, sz;
        sincosf(0.5f * t0, &sx, &cx);
        sincosf(0.5f * t1, &sy, &cy);
        sincosf(0.5f * t2, &sz, &cz);
        const float2 m00 = make_float2( cy * cx,  sy * sx);
        const float2 m01 = make_float2(-sy * cx, -cy * sx);
        const float2 ezm = make_float2(cz, -sz);
        U[t][0] = cmul(ezm, m00);   // u00
        U[t][1] = cmul(ezm, m01);   // u01 (u10=-conj(u01), u11=conj(u00))
    }

    // transpose permutation (self-inverse): swap index bits [9:5] <-> [4:0].
    // Layout A: thread t holds amp t (lane bits = qubits 5..9).
    // Layout B: thread t holds amp Pt (lane bits = qubits 0..4).
    const int Pt = ((t & 31) << 5) | (t >> 5);

    // forward ring permutation C (descending e): s_new[i] = s_old[C(i)]
    int Ct = t;
    #pragma unroll
    for (int e = NQ - 1; e >= 0; e--) {
        const int c  = (e < NQ - 1) ? e : NQ - 1;
        const int tq = (e < NQ - 1) ? e + 1 : 0;
        const int cm = 1 << (NQ - 1 - c);
        const int tm = 1 << (NQ - 1 - tq);
        Ct ^= (Ct & cm) ? tm : 0;
    }
    // inverse ring C^-1 (ascending e) applied to the layout-B index held at
    // the end of layer 4 (final gather skipped; ring folded into Z masks)
    int Jf = Pt;
    #pragma unroll
    for (int e = 0; e < NQ; e++) {
        const int c  = (e < NQ - 1) ? e : NQ - 1;
        const int tq = (e < NQ - 1) ? e + 1 : 0;
        const int cm = 1 << (NQ - 1 - c);
        const int tm = 1 << (NQ - 1 - tq);
        Jf ^= (Jf & cm) ? tm : 0;
    }

    // per-slot sign from lane bit (4-k); identical for layouts A and B
    float sgn[5];
    #pragma unroll
    for (int k = 0; k < 5; k++) sgn[k] = (lane & (16 >> k)) ? -1.0f : 1.0f;

    __syncthreads();   // U ready

    // ---- layer 1 analytic: a(t) = psi(C(t)), psi = product state ----------
    float2 a;
    {
        float2 p;
        #pragma unroll
        for (int q = 0; q < NQ; q++) {
            const float2 u00 = U[q][0];
            const float2 u01 = U[q][1];
            const float2 u10 = make_float2(-u01.x, u01.y);
            const float2 v = ((Ct >> (9 - q)) & 1) ? u10 : u00;
            if (q == 0) p = v;
            else        p = cmul(p, v);
        }
        a = p;
    }

    // ---- layers 2..4 ------------------------------------------------------
    int cur = 0;
    #pragma unroll 1
    for (int l = 1; l < NL; l++) {
        // qubits 5..9 on lane bits (layout A)
        #pragma unroll
        for (int k = 0; k < 5; k++) {
            const int g = l * NQ + 5 + k;
            float2 u0 = U[g][0];
            float2 u1 = U[g][1];
            const float s = sgn[k];
            u0.y *= s; u1.x *= s;
            const int m = 16 >> k;
            float2 bv;
            bv.x = __shfl_xor_sync(0xffffffffu, a.x, m);
            bv.y = __shfl_xor_sync(0xffffffffu, a.y, m);
            a = cfma2(u0, a, u1, bv);
        }
        // transpose A -> B
        st[cur][SIDX(t)] = a;
        __syncthreads();
        a = st[cur][SIDX(Pt)];
        cur ^= 1;
        // qubits 0..4 on lane bits (layout B)
        #pragma unroll
        for (int k = 0; k < 5; k++) {
            const int g = l * NQ + k;
            float2 u0 = U[g][0];
            float2 u1 = U[g][1];
            const float s = sgn[k];
            u0.y *= s; u1.x *= s;
            const int m = 16 >> k;
            float2 bv;
            bv.x = __shfl_xor_sync(0xffffffffu, a.x, m);
            bv.y = __shfl_xor_sync(0xffffffffu, a.y, m);
            a = cfma2(u0, a, u1, bv);
        }
        if (l < NL - 1) {
            // CNOT ring + transpose back: write natural order, gather C(t)
            st[cur][SIDX(Pt)] = a;
            __syncthreads();
            a = st[cur][SIDX(Ct)];
            cur ^= 1;
        }
    }

    // <Z_q> with the final ring folded in: mass |a|^2 sits at final index Jf
    const float p = fmaf(a.x, a.x, a.y * a.y);
    #pragma unroll
    for (int q = 0; q < NQ; q++) {
        const int mask = 1 << (NQ - 1 - q);
        float v = (Jf & mask) ? p : 0.0f;
        #pragma unroll
        for (int o = 16; o > 0; o >>= 1) v += __shfl_xor_sync(0xffffffffu, v, o);
        if (lane == 0) wsum[warp][q] = v;
    }
    __syncthreads();
    if (t < NQ) {
        float s = 0.0f;
        #pragma unroll
        for (int w = 0; w < 32; w++) s += wsum[w][t];
        g_z[t] = 1.0f - 2.0f * s;
    }
    __syncthreads();
    if (t == 0) {
        __threadfence();
        atomicMax(&g_zflag, target);   // release; monotonic
    }
}

// ---------------------------------------------------------------------------
// Kernel C: broadcast fill — 64MB of float4 stores. This shape measured at
// the LTS write cap (~6300 B/cyc at current DVFS clocks); proven engine.
// ---------------------------------------------------------------------------
__global__ void __launch_bounds__(256)
fill_kernel(float4* __restrict__ out) {
    const int col = threadIdx.x;
    const float4 v = ((const float4*)g_y)[col];
    const size_t base = (size_t)blockIdx.x * 4;
    #pragma unroll
    for (int r = 0; r < 4; r++) {
        out[(base + r) * (EDIM / 4) + col] = v;
    }
}

// ---------------------------------------------------------------------------
// inputs: 0=x, 1=W_in, 2=b_in, 3=params, 4=W1, 5=b1, 6=W2, 7=b2
// x / W_in / b_in are dead in the reference.
// ---------------------------------------------------------------------------
extern "C" void kernel_launch(void* const* d_in, const int* in_sizes, int n_in,
                              void* d_out, int out_size) {
    const float* params = (const float*)d_in[3];
    const float* W1     = (const float*)d_in[4];
    const float* b1     = (const float*)d_in[5];
    const float* W2     = (const float*)d_in[6];
    const float* b2     = (const float*)d_in[7];
    float* out = (float*)d_out;

    circuit_h_y_kernel<<<GRID_A, 1024>>>(params, W1, b1, W2, b2);
    fill_kernel<<<NTOK / 4, 256>>>((float4*)out);
}